// round 3
// baseline (speedup 1.0000x reference)
#include <cuda_runtime.h>
#include <math.h>

#define NH 12
#define NB 4
#define SEQ 1024
#define CH 768
#define HD 64
#define BHD 48   // NB*NH
#define QKVLD 2304

// -------- scratch (no allocs allowed) --------
__device__ float g_qkv[NB * SEQ * 3 * CH];   // (4096, 2304)
__device__ float g_relh[BHD * SEQ * 32];     // (48,1024,32)
__device__ float g_relw[BHD * SEQ * 32];
__device__ float g_attn[NB * SEQ * CH];      // (4096, 768)

// ============================================================
// GEMM: C[M,N] = A[M,K] @ B[K,N] (+ bias).  BM=BN=64, BK=16,
// 256 threads, 4x4 microtile. M%64==0, N%64==0, K%16==0.
// ============================================================
template <bool BIAS>
__global__ void gemm64x64(const float* __restrict__ A, const float* __restrict__ B,
                          const float* __restrict__ bias, float* __restrict__ Cm,
                          int M, int N, int K) {
    __shared__ float As[16][64];
    __shared__ float Bs[16][64];
    int tid = threadIdx.x;
    int tx = tid & 15, ty = tid >> 4;
    int bm = blockIdx.y * 64, bn = blockIdx.x * 64;

    int arow = tid >> 2;           // 0..63
    int acol = (tid & 3) * 4;      // 0,4,8,12
    int brow = tid >> 4;           // 0..15
    int bcol = (tid & 15) * 4;     // 0..60

    float acc[4][4] = {};

    for (int k0 = 0; k0 < K; k0 += 16) {
        float4 av = *reinterpret_cast<const float4*>(&A[(size_t)(bm + arow) * K + k0 + acol]);
        float4 bv = *reinterpret_cast<const float4*>(&B[(size_t)(k0 + brow) * N + bn + bcol]);
        As[acol + 0][arow] = av.x;
        As[acol + 1][arow] = av.y;
        As[acol + 2][arow] = av.z;
        As[acol + 3][arow] = av.w;
        *reinterpret_cast<float4*>(&Bs[brow][bcol]) = bv;
        __syncthreads();
#pragma unroll
        for (int kk = 0; kk < 16; kk++) {
            float a[4], b[4];
#pragma unroll
            for (int i = 0; i < 4; i++) a[i] = As[kk][ty * 4 + i];
#pragma unroll
            for (int j = 0; j < 4; j++) b[j] = Bs[kk][tx * 4 + j];
#pragma unroll
            for (int i = 0; i < 4; i++)
#pragma unroll
                for (int j = 0; j < 4; j++)
                    acc[i][j] = fmaf(a[i], b[j], acc[i][j]);
        }
        __syncthreads();
    }
#pragma unroll
    for (int i = 0; i < 4; i++) {
        int row = bm + ty * 4 + i;
#pragma unroll
        for (int j = 0; j < 4; j++) {
            int col = bn + tx * 4 + j;
            float v = acc[i][j];
            if (BIAS) v += bias[col];
            Cm[(size_t)row * N + col] = v;
        }
    }
}

// ============================================================
// Relative position bias:
//   relh[bh,q,kh] = sum_d q[bh,q,d] * rph[(qh-kh+31), d]
//   relw[bh,q,kw] = sum_d q[bh,q,d] * rpw[(qw-kw+31), d]
// One block (64 threads) per (bh,q).
// ============================================================
__global__ void relpos_kernel(const float* __restrict__ rph, const float* __restrict__ rpw) {
    int blk = blockIdx.x;            // bh*SEQ + q
    int bh = blk >> 10;
    int q = blk & 1023;
    int b = bh / NH, head = bh % NH;
    int qh = q >> 5, qw = q & 31;

    __shared__ float qs[HD];
    int t = threadIdx.x;
    qs[t] = g_qkv[(size_t)(b * SEQ + q) * QKVLD + head * HD + t];
    __syncthreads();

    if (t < 32) {
        const float* r = &rph[(qh - t + 31) * HD];
        float acc = 0.f;
#pragma unroll
        for (int d = 0; d < HD; d++) acc = fmaf(qs[d], r[d], acc);
        g_relh[(size_t)blk * 32 + t] = acc;
    } else {
        int kw = t - 32;
        const float* r = &rpw[(qw - kw + 31) * HD];
        float acc = 0.f;
#pragma unroll
        for (int d = 0; d < HD; d++) acc = fmaf(qs[d], r[d], acc);
        g_relw[(size_t)blk * 32 + kw] = acc;
    }
}

// ============================================================
// Flash-style attention. Bq=Bk=64, hd=64, 256 threads,
// 4x4 microtiles for both QK^T and PV. Online softmax.
// Grid: (SEQ/64, BHD)
// ============================================================
#define LDS 65
#define ATTN_SMEM ((4 * 64 * LDS + 3 * 64) * 4)

__global__ void attn_kernel() {
    extern __shared__ float sm[];
    float* Qs = sm;                  // 64 x LDS
    float* Ks = Qs + 64 * LDS;
    float* Vs = Ks + 64 * LDS;
    float* Ss = Vs + 64 * LDS;
    float* mrow = Ss + 64 * LDS;     // 64
    float* lrow = mrow + 64;         // 64
    float* crow = lrow + 64;         // 64

    int tid = threadIdx.x;
    int tx = tid & 15, ty = tid >> 4;
    int bh = blockIdx.y;
    int b = bh / NH, head = bh % NH;
    int qbase = blockIdx.x * 64;

    const float* base = &g_qkv[(size_t)b * SEQ * QKVLD + head * HD];

    // load Q tile
    for (int i = tid; i < 64 * 16; i += 256) {
        int r = i >> 4;
        int dc = (i & 15) * 4;
        float4 v = *reinterpret_cast<const float4*>(&base[(size_t)(qbase + r) * QKVLD + dc]);
        Qs[r * LDS + dc + 0] = v.x;
        Qs[r * LDS + dc + 1] = v.y;
        Qs[r * LDS + dc + 2] = v.z;
        Qs[r * LDS + dc + 3] = v.w;
    }
    if (tid < 64) { mrow[tid] = -INFINITY; lrow[tid] = 0.f; }
    __syncthreads();

    float oacc[4][4] = {};
    const float scale = 0.125f;   // 64^-0.5
    const float* relh = &g_relh[(size_t)bh * SEQ * 32];
    const float* relw = &g_relw[(size_t)bh * SEQ * 32];

    for (int kt = 0; kt < 16; kt++) {
        int kbase = kt * 64;
        // load K/V tiles
        for (int i = tid; i < 64 * 16; i += 256) {
            int r = i >> 4;
            int dc = (i & 15) * 4;
            const float* kp = &base[(size_t)(kbase + r) * QKVLD + CH + dc];
            float4 kv = *reinterpret_cast<const float4*>(kp);
            Ks[r * LDS + dc + 0] = kv.x;
            Ks[r * LDS + dc + 1] = kv.y;
            Ks[r * LDS + dc + 2] = kv.z;
            Ks[r * LDS + dc + 3] = kv.w;
            float4 vv = *reinterpret_cast<const float4*>(kp + CH);
            Vs[r * LDS + dc + 0] = vv.x;
            Vs[r * LDS + dc + 1] = vv.y;
            Vs[r * LDS + dc + 2] = vv.z;
            Vs[r * LDS + dc + 3] = vv.w;
        }
        __syncthreads();

        // S = scale * Q K^T + bias
        float sacc[4][4] = {};
#pragma unroll 8
        for (int d = 0; d < 64; d++) {
            float a[4], bb[4];
#pragma unroll
            for (int i = 0; i < 4; i++) a[i] = Qs[(ty * 4 + i) * LDS + d];
#pragma unroll
            for (int j = 0; j < 4; j++) bb[j] = Ks[(tx * 4 + j) * LDS + d];
#pragma unroll
            for (int i = 0; i < 4; i++)
#pragma unroll
                for (int j = 0; j < 4; j++)
                    sacc[i][j] = fmaf(a[i], bb[j], sacc[i][j]);
        }
#pragma unroll
        for (int i = 0; i < 4; i++) {
            int qrow = qbase + ty * 4 + i;
#pragma unroll
            for (int j = 0; j < 4; j++) {
                int k = kbase + tx * 4 + j;
                float bias = relh[(size_t)qrow * 32 + (k >> 5)] +
                             relw[(size_t)qrow * 32 + (k & 31)];
                Ss[(ty * 4 + i) * LDS + tx * 4 + j] = fmaf(scale, sacc[i][j], bias);
            }
        }
        __syncthreads();

        // online softmax row stats
        if (tid < 64) {
            float* row = &Ss[tid * LDS];
            float mx = -INFINITY;
#pragma unroll 8
            for (int c = 0; c < 64; c++) mx = fmaxf(mx, row[c]);
            float mo = mrow[tid];
            float mn = fmaxf(mo, mx);
            float cr = __expf(mo - mn);
            float sum = 0.f;
#pragma unroll 8
            for (int c = 0; c < 64; c++) {
                float p = __expf(row[c] - mn);
                row[c] = p;
                sum += p;
            }
            mrow[tid] = mn;
            lrow[tid] = lrow[tid] * cr + sum;
            crow[tid] = cr;
        }
        __syncthreads();

        // O = O*corr + P @ V
        float cr[4];
#pragma unroll
        for (int i = 0; i < 4; i++) cr[i] = crow[ty * 4 + i];
#pragma unroll
        for (int i = 0; i < 4; i++)
#pragma unroll
            for (int j = 0; j < 4; j++) oacc[i][j] *= cr[i];
#pragma unroll 8
        for (int j64 = 0; j64 < 64; j64++) {
            float p[4], v[4];
#pragma unroll
            for (int i = 0; i < 4; i++) p[i] = Ss[(ty * 4 + i) * LDS + j64];
#pragma unroll
            for (int c = 0; c < 4; c++) v[c] = Vs[j64 * LDS + tx * 4 + c];
#pragma unroll
            for (int i = 0; i < 4; i++)
#pragma unroll
                for (int c = 0; c < 4; c++)
                    oacc[i][c] = fmaf(p[i], v[c], oacc[i][c]);
        }
        __syncthreads();
    }

    // normalize + write to (B,S,hn,hd) = (B,S,C) layout for out-proj
#pragma unroll
    for (int i = 0; i < 4; i++) {
        int q = qbase + ty * 4 + i;
        float inv = 1.f / lrow[ty * 4 + i];
#pragma unroll
        for (int j = 0; j < 4; j++) {
            g_attn[(size_t)(b * SEQ + q) * CH + head * HD + tx * 4 + j] = oacc[i][j] * inv;
        }
    }
}

// ============================================================
extern "C" void kernel_launch(void* const* d_in, const int* in_sizes, int n_in,
                              void* d_out, int out_size) {
    const float* x     = (const float*)d_in[0];
    const float* Wqkv  = (const float*)d_in[1];
    const float* Wproj = (const float*)d_in[2];
    const float* bproj = (const float*)d_in[3];
    const float* rph   = (const float*)d_in[4];
    const float* rpw   = (const float*)d_in[5];
    float* out = (float*)d_out;

    float* qkv;  cudaGetSymbolAddress((void**)&qkv,  g_qkv);
    float* attn; cudaGetSymbolAddress((void**)&attn, g_attn);

    // 1) QKV projection: (4096 x 2304) = (4096 x 768) @ (768 x 2304)
    gemm64x64<false><<<dim3(QKVLD / 64, (NB * SEQ) / 64), 256>>>(
        x, Wqkv, nullptr, qkv, NB * SEQ, QKVLD, CH);

    // 2) decomposed relative position bias
    relpos_kernel<<<BHD * SEQ, 64>>>(rph, rpw);

    // 3) attention with online softmax
    cudaFuncSetAttribute(attn_kernel, cudaFuncAttributeMaxDynamicSharedMemorySize, ATTN_SMEM);
    attn_kernel<<<dim3(SEQ / 64, BHD), 256, ATTN_SMEM>>>();

    // 4) out projection + bias: (4096 x 768) = (4096 x 768) @ (768 x 768) + b
    gemm64x64<true><<<dim3(CH / 64, (NB * SEQ) / 64), 256>>>(
        attn, Wproj, bproj, out, NB * SEQ, CH, CH);
}

// round 4
// speedup vs baseline: 2.4779x; 2.4779x over previous
#include <cuda_runtime.h>
#include <math.h>

#define NH 12
#define NB 4
#define SEQ 1024
#define CH 768
#define HD 64
#define BHD 48   // NB*NH
#define QKVLD 2304

// -------- scratch (no allocs allowed) --------
__device__ float g_qkv[NB * SEQ * 3 * CH];   // (4096, 2304)
__device__ float g_relh[BHD * SEQ * 32];
__device__ float g_relw[BHD * SEQ * 32];
__device__ float g_attn[NB * SEQ * CH];      // (4096, 768)

__device__ __forceinline__ unsigned f2tf(float f) {
    unsigned u; asm("cvt.rna.tf32.f32 %0, %1;" : "=r"(u) : "f"(f)); return u;
}

// D += A*B, m16n8k8 tf32. a: {(g,t),(g+8,t),(g,t+4),(g+8,t+4)}  b: {(t,g),(t+4,g)}
__device__ __forceinline__ void mma_tf32(float* d, const unsigned* a, const unsigned* b) {
    asm volatile(
        "mma.sync.aligned.m16n8k8.row.col.f32.tf32.tf32.f32 "
        "{%0,%1,%2,%3}, {%4,%5,%6,%7}, {%8,%9}, {%0,%1,%2,%3};\n"
        : "+f"(d[0]), "+f"(d[1]), "+f"(d[2]), "+f"(d[3])
        : "r"(a[0]), "r"(a[1]), "r"(a[2]), "r"(a[3]), "r"(b[0]), "r"(b[1]));
}

// ============================================================
// TF32 GEMM: C[M,N] = A[M,K] @ B[K,N] (+bias).
// Block 128x128, BK=32, 256 threads, 8 warps (2m x 4n), warp tile 64x32.
// ============================================================
template <bool BIAS>
__global__ __launch_bounds__(256) void gemm_tf32(
    const float* __restrict__ A, const float* __restrict__ B,
    const float* __restrict__ bias, float* __restrict__ Cm,
    int M, int N, int K) {
    __shared__ unsigned As[32][132];   // k-major: As[k][m]
    __shared__ unsigned Bs[32][132];   // Bs[k][n]

    int tid = threadIdx.x;
    int lane = tid & 31, w = tid >> 5;
    int g = lane >> 2, t4 = lane & 3;
    int wm = (w & 1) * 64, wn = (w >> 1) * 32;
    int bm = blockIdx.y * 128, bn = blockIdx.x * 128;

    const int a_r = tid >> 3, a_k = (tid & 7) * 4;     // A: 128 rows x 8 float4
    const int b_r = tid >> 5, b_c = (tid & 31) * 4;    // B: 32 rows x 32 float4

    float acc[4][4][4];
#pragma unroll
    for (int i = 0; i < 4; i++)
#pragma unroll
        for (int j = 0; j < 4; j++)
#pragma unroll
            for (int r = 0; r < 4; r++) acc[i][j][r] = 0.f;

    float4 areg[4], breg[4];
#pragma unroll
    for (int ii = 0; ii < 4; ii++) {
        areg[ii] = *(const float4*)&A[(size_t)(bm + a_r + 32 * ii) * K + a_k];
        breg[ii] = *(const float4*)&B[(size_t)(b_r + 8 * ii) * N + bn + b_c];
    }

    for (int k0 = 0; k0 < K; k0 += 32) {
        __syncthreads();
#pragma unroll
        for (int ii = 0; ii < 4; ii++) {
            int r = a_r + 32 * ii;
            As[a_k + 0][r] = f2tf(areg[ii].x);
            As[a_k + 1][r] = f2tf(areg[ii].y);
            As[a_k + 2][r] = f2tf(areg[ii].z);
            As[a_k + 3][r] = f2tf(areg[ii].w);
            uint4 bv;
            bv.x = f2tf(breg[ii].x); bv.y = f2tf(breg[ii].y);
            bv.z = f2tf(breg[ii].z); bv.w = f2tf(breg[ii].w);
            *(uint4*)&Bs[b_r + 8 * ii][b_c] = bv;
        }
        __syncthreads();
        if (k0 + 32 < K) {
            int kn = k0 + 32;
#pragma unroll
            for (int ii = 0; ii < 4; ii++) {
                areg[ii] = *(const float4*)&A[(size_t)(bm + a_r + 32 * ii) * K + kn + a_k];
                breg[ii] = *(const float4*)&B[(size_t)(kn + b_r + 8 * ii) * N + bn + b_c];
            }
        }
#pragma unroll
        for (int c = 0; c < 4; c++) {
            unsigned af[4][4], bf[4][2];
#pragma unroll
            for (int i = 0; i < 4; i++) {
                af[i][0] = As[c * 8 + t4][wm + 16 * i + g];
                af[i][1] = As[c * 8 + t4][wm + 16 * i + g + 8];
                af[i][2] = As[c * 8 + t4 + 4][wm + 16 * i + g];
                af[i][3] = As[c * 8 + t4 + 4][wm + 16 * i + g + 8];
            }
#pragma unroll
            for (int j = 0; j < 4; j++) {
                bf[j][0] = Bs[c * 8 + t4][wn + 8 * j + g];
                bf[j][1] = Bs[c * 8 + t4 + 4][wn + 8 * j + g];
            }
#pragma unroll
            for (int i = 0; i < 4; i++)
#pragma unroll
                for (int j = 0; j < 4; j++)
                    mma_tf32(acc[i][j], af[i], bf[j]);
        }
    }

#pragma unroll
    for (int i = 0; i < 4; i++)
#pragma unroll
        for (int j = 0; j < 4; j++) {
            int row = bm + wm + 16 * i + g;
            int col = bn + wn + 8 * j + 2 * t4;
            float2 v0 = make_float2(acc[i][j][0], acc[i][j][1]);
            float2 v1 = make_float2(acc[i][j][2], acc[i][j][3]);
            if (BIAS) {
                float2 bb = *(const float2*)&bias[col];
                v0.x += bb.x; v0.y += bb.y; v1.x += bb.x; v1.y += bb.y;
            }
            *(float2*)&Cm[(size_t)row * N + col] = v0;
            *(float2*)&Cm[(size_t)(row + 8) * N + col] = v1;
        }
}

// ============================================================
// Relative position bias. Block = (q-chunk of 128, bh). 256 threads.
// thread -> (q_local = tid>>1, half = tid&1): 32 dot-products of length 64.
// ============================================================
__global__ __launch_bounds__(256) void relpos_kernel(
    const float* __restrict__ rph, const float* __restrict__ rpw) {
    __shared__ float Rh[63 * 68], Rw[63 * 68];
    int tid = threadIdx.x;
    int qc = blockIdx.x, bh = blockIdx.y;

    for (int idx = tid; idx < 63 * 64; idx += 256) {
        int row = idx >> 6, d = idx & 63;
        Rh[row * 68 + d] = rph[idx];
        Rw[row * 68 + d] = rpw[idx];
    }
    __syncthreads();

    int ql = tid >> 1, half = tid & 1;
    int q = qc * 128 + ql;
    int b = bh / NH, head = bh % NH;
    int pc = half ? (q & 31) : (q >> 5);
    const float* qptr = &g_qkv[(size_t)(b * SEQ + q) * QKVLD + head * HD];
    const float* T = half ? Rw : Rh;

    float acc[32];
#pragma unroll
    for (int o = 0; o < 32; o++) acc[o] = 0.f;

    for (int d0 = 0; d0 < 64; d0 += 8) {
        float4 v0 = *(const float4*)&qptr[d0];
        float4 v1 = *(const float4*)&qptr[d0 + 4];
        float qd[8] = {v0.x, v0.y, v0.z, v0.w, v1.x, v1.y, v1.z, v1.w};
#pragma unroll
        for (int dd = 0; dd < 8; dd++) {
            float qv = qd[dd];
            const float* Tp = &T[(pc + 31) * 68 + d0 + dd];
#pragma unroll
            for (int o = 0; o < 32; o++)
                acc[o] = fmaf(qv, Tp[-o * 68], acc[o]);
        }
    }
    float* dst = half ? &g_relw[((size_t)bh * SEQ + q) * 32]
                      : &g_relh[((size_t)bh * SEQ + q) * 32];
#pragma unroll
    for (int o = 0; o < 32; o++) dst[o] = acc[o];
}

// ============================================================
// Flash attention with tf32 MMA. Bq=Bk=64, 256 threads, 8 warps (2m x 4n),
// warp tile 32x16. O kept in C-fragments across kv tiles.
// ============================================================
#define ALD 65   // transposed tiles [d-or-k][m]
#define VLD 68   // row-major tiles  [k][n] / scores [m][k]
#define ATTN_SMEM ((3 * 64 * ALD + 2 * 64 * VLD + 2 * 64 * 32 + 3 * 64) * 4)

__global__ __launch_bounds__(256) void attn_mma() {
    extern __shared__ unsigned smu[];
    unsigned* Qs = smu;                       // [64][ALD]  Qs[d*ALD + m]
    unsigned* Ks = Qs + 64 * ALD;             // [64][ALD]  Ks[d*ALD + n]
    unsigned* Ps = Ks + 64 * ALD;             // [64][ALD]  Ps[k*ALD + m]
    unsigned* Vs = Ps + 64 * ALD;             // [64][VLD]  Vs[k*VLD + n]
    float* Ss   = (float*)(Vs + 64 * VLD);    // [64][VLD]  raw scores
    float* relh = Ss + 64 * VLD;              // [64][32]
    float* relw = relh + 64 * 32;             // [64][32]
    float* mrow = relw + 64 * 32;
    float* lrow = mrow + 64;
    float* crow = lrow + 64;

    int tid = threadIdx.x;
    int lane = tid & 31, w = tid >> 5;
    int g = lane >> 2, t4 = lane & 3;
    int wm = (w >> 2) * 32, wn = (w & 3) * 16;

    int bh = blockIdx.y, qbase = blockIdx.x * 64;
    int b = bh / NH, head = bh % NH;
    const float* base = &g_qkv[(size_t)b * SEQ * QKVLD + head * HD];

    const int r_ = tid >> 4, d4_ = (tid & 15) * 4;
#pragma unroll
    for (int ii = 0; ii < 4; ii++) {
        int row = r_ + 16 * ii;
        float4 v = *(const float4*)&base[(size_t)(qbase + row) * QKVLD + d4_];
        Qs[(d4_ + 0) * ALD + row] = f2tf(v.x);
        Qs[(d4_ + 1) * ALD + row] = f2tf(v.y);
        Qs[(d4_ + 2) * ALD + row] = f2tf(v.z);
        Qs[(d4_ + 3) * ALD + row] = f2tf(v.w);
    }
    {
        const float* gh = &g_relh[((size_t)bh * SEQ + qbase) * 32];
        const float* gw = &g_relw[((size_t)bh * SEQ + qbase) * 32];
        for (int idx = tid; idx < 512; idx += 256) {
            ((float4*)relh)[idx] = ((const float4*)gh)[idx];
            ((float4*)relw)[idx] = ((const float4*)gw)[idx];
        }
    }
    if (tid < 64) { mrow[tid] = -1e30f; lrow[tid] = 0.f; }

    float oacc[2][2][4];
#pragma unroll
    for (int i = 0; i < 2; i++)
#pragma unroll
        for (int j = 0; j < 2; j++)
#pragma unroll
            for (int r = 0; r < 4; r++) oacc[i][j][r] = 0.f;

    for (int kt = 0; kt < 16; kt++) {
        __syncthreads();
        // load K (transposed) and V (row-major) tiles, cvt to tf32
#pragma unroll
        for (int ii = 0; ii < 4; ii++) {
            int row = r_ + 16 * ii;
            const float* kp = &base[(size_t)(kt * 64 + row) * QKVLD + CH + d4_];
            float4 kv = *(const float4*)kp;
            Ks[(d4_ + 0) * ALD + row] = f2tf(kv.x);
            Ks[(d4_ + 1) * ALD + row] = f2tf(kv.y);
            Ks[(d4_ + 2) * ALD + row] = f2tf(kv.z);
            Ks[(d4_ + 3) * ALD + row] = f2tf(kv.w);
            float4 vv = *(const float4*)(kp + CH);
            uint4 u;
            u.x = f2tf(vv.x); u.y = f2tf(vv.y); u.z = f2tf(vv.z); u.w = f2tf(vv.w);
            *(uint4*)&Vs[row * VLD + d4_] = u;
        }
        __syncthreads();

        // S = Q @ K^T (raw, fp32 accum)
        float sacc[2][2][4];
#pragma unroll
        for (int i = 0; i < 2; i++)
#pragma unroll
            for (int j = 0; j < 2; j++)
#pragma unroll
                for (int r = 0; r < 4; r++) sacc[i][j][r] = 0.f;
#pragma unroll
        for (int c = 0; c < 8; c++) {
            unsigned af[2][4], bf[2][2];
#pragma unroll
            for (int i = 0; i < 2; i++) {
                af[i][0] = Qs[(c * 8 + t4) * ALD + wm + 16 * i + g];
                af[i][1] = Qs[(c * 8 + t4) * ALD + wm + 16 * i + g + 8];
                af[i][2] = Qs[(c * 8 + t4 + 4) * ALD + wm + 16 * i + g];
                af[i][3] = Qs[(c * 8 + t4 + 4) * ALD + wm + 16 * i + g + 8];
            }
#pragma unroll
            for (int j = 0; j < 2; j++) {
                bf[j][0] = Ks[(c * 8 + t4) * ALD + wn + 8 * j + g];
                bf[j][1] = Ks[(c * 8 + t4 + 4) * ALD + wn + 8 * j + g];
            }
#pragma unroll
            for (int i = 0; i < 2; i++)
#pragma unroll
                for (int j = 0; j < 2; j++)
                    mma_tf32(sacc[i][j], af[i], bf[j]);
        }
#pragma unroll
        for (int i = 0; i < 2; i++)
#pragma unroll
            for (int j = 0; j < 2; j++) {
                int row = wm + 16 * i + g, col = wn + 8 * j + 2 * t4;
                *(float2*)&Ss[row * VLD + col] = make_float2(sacc[i][j][0], sacc[i][j][1]);
                *(float2*)&Ss[(row + 8) * VLD + col] = make_float2(sacc[i][j][2], sacc[i][j][3]);
            }
        __syncthreads();

        // online softmax: 4 lanes per row, 16 cols each
        {
            int row = tid >> 2, qq = tid & 3;
            float vals[16];
            float ml = -1e30f;
            int khb = 2 * kt;
#pragma unroll
            for (int cc = 0; cc < 16; cc++) {
                int col = qq * 16 + cc;
                float s = 0.125f * Ss[row * VLD + col]
                        + relh[row * 32 + khb + (col >> 5)]
                        + relw[row * 32 + (col & 31)];
                vals[cc] = s;
                ml = fmaxf(ml, s);
            }
            ml = fmaxf(ml, __shfl_xor_sync(0xffffffffu, ml, 1));
            ml = fmaxf(ml, __shfl_xor_sync(0xffffffffu, ml, 2));
            float mo = mrow[row];
            float mn = fmaxf(mo, ml);
            float sum = 0.f;
#pragma unroll
            for (int cc = 0; cc < 16; cc++) {
                int col = qq * 16 + cc;
                float p = __expf(vals[cc] - mn);
                sum += p;
                Ps[col * ALD + row] = f2tf(p);
            }
            sum += __shfl_xor_sync(0xffffffffu, sum, 1);
            sum += __shfl_xor_sync(0xffffffffu, sum, 2);
            if (qq == 0) {
                float cr = __expf(mo - mn);
                mrow[row] = mn;
                lrow[row] = lrow[row] * cr + sum;
                crow[row] = cr;
            }
        }
        __syncthreads();

        // rescale O, then O += P @ V
        float cr[2][2];
#pragma unroll
        for (int i = 0; i < 2; i++) {
            cr[i][0] = crow[wm + 16 * i + g];
            cr[i][1] = crow[wm + 16 * i + g + 8];
        }
#pragma unroll
        for (int i = 0; i < 2; i++)
#pragma unroll
            for (int j = 0; j < 2; j++) {
                oacc[i][j][0] *= cr[i][0]; oacc[i][j][1] *= cr[i][0];
                oacc[i][j][2] *= cr[i][1]; oacc[i][j][3] *= cr[i][1];
            }
#pragma unroll
        for (int c = 0; c < 8; c++) {
            unsigned af[2][4], bf[2][2];
#pragma unroll
            for (int i = 0; i < 2; i++) {
                af[i][0] = Ps[(c * 8 + t4) * ALD + wm + 16 * i + g];
                af[i][1] = Ps[(c * 8 + t4) * ALD + wm + 16 * i + g + 8];
                af[i][2] = Ps[(c * 8 + t4 + 4) * ALD + wm + 16 * i + g];
                af[i][3] = Ps[(c * 8 + t4 + 4) * ALD + wm + 16 * i + g + 8];
            }
#pragma unroll
            for (int j = 0; j < 2; j++) {
                bf[j][0] = Vs[(c * 8 + t4) * VLD + wn + 8 * j + g];
                bf[j][1] = Vs[(c * 8 + t4 + 4) * VLD + wn + 8 * j + g];
            }
#pragma unroll
            for (int i = 0; i < 2; i++)
#pragma unroll
                for (int j = 0; j < 2; j++)
                    mma_tf32(oacc[i][j], af[i], bf[j]);
        }
    }

    // normalize + write to (B,S,C) layout
#pragma unroll
    for (int i = 0; i < 2; i++) {
        float inv0 = 1.f / lrow[wm + 16 * i + g];
        float inv1 = 1.f / lrow[wm + 16 * i + g + 8];
#pragma unroll
        for (int j = 0; j < 2; j++) {
            int q = qbase + wm + 16 * i + g;
            int col = head * HD + wn + 8 * j + 2 * t4;
            float* op = &g_attn[(size_t)(b * SEQ + q) * CH + col];
            *(float2*)op = make_float2(oacc[i][j][0] * inv0, oacc[i][j][1] * inv0);
            *(float2*)(op + 8 * CH) = make_float2(oacc[i][j][2] * inv1, oacc[i][j][3] * inv1);
        }
    }
}

// ============================================================
extern "C" void kernel_launch(void* const* d_in, const int* in_sizes, int n_in,
                              void* d_out, int out_size) {
    const float* x     = (const float*)d_in[0];
    const float* Wqkv  = (const float*)d_in[1];
    const float* Wproj = (const float*)d_in[2];
    const float* bproj = (const float*)d_in[3];
    const float* rph   = (const float*)d_in[4];
    const float* rpw   = (const float*)d_in[5];
    float* out = (float*)d_out;

    float* qkv;  cudaGetSymbolAddress((void**)&qkv,  g_qkv);
    float* attn; cudaGetSymbolAddress((void**)&attn, g_attn);

    // 1) QKV projection: (4096 x 2304) = (4096 x 768) @ (768 x 2304)
    gemm_tf32<false><<<dim3(QKVLD / 128, (NB * SEQ) / 128), 256>>>(
        x, Wqkv, nullptr, qkv, NB * SEQ, QKVLD, CH);

    // 2) decomposed relative position bias
    relpos_kernel<<<dim3(8, BHD), 256>>>(rph, rpw);

    // 3) attention (tf32 mma + online softmax)
    cudaFuncSetAttribute(attn_mma, cudaFuncAttributeMaxDynamicSharedMemorySize, ATTN_SMEM);
    attn_mma<<<dim3(SEQ / 64, BHD), 256, ATTN_SMEM>>>();

    // 4) out projection + bias: (4096 x 768) = (4096 x 768) @ (768 x 768) + b
    gemm_tf32<true><<<dim3(CH / 128, (NB * SEQ) / 128), 256>>>(
        attn, Wproj, bproj, out, NB * SEQ, CH, CH);
}

// round 7
// speedup vs baseline: 4.6077x; 1.8596x over previous
#include <cuda_runtime.h>
#include <math.h>

#define NH 12
#define NB 4
#define SEQ 1024
#define CH 768
#define HD 64
#define BHD 48   // NB*NH
#define QKVLD 2304
#define LOG2E 1.4426950408889634f

// -------- scratch (no allocs allowed) --------
__device__ float g_qkv[NB * SEQ * 3 * CH];   // (4096, 2304)
__device__ float g_relh[BHD * SEQ * 32];
__device__ float g_relw[BHD * SEQ * 32];
__device__ float g_attn[NB * SEQ * CH];      // (4096, 768)

__device__ __forceinline__ unsigned f2tf(float f) {
    unsigned u; asm("cvt.rna.tf32.f32 %0, %1;" : "=r"(u) : "f"(f)); return u;
}
__device__ __forceinline__ float ex2(float x) {
    float y; asm("ex2.approx.ftz.f32 %0, %1;" : "=f"(y) : "f"(x)); return y;
}

// D += A*B, m16n8k8 tf32. a: {(g,t),(g+8,t),(g,t+4),(g+8,t+4)}  b: {(t,g),(t+4,g)}
// c: {(g,2t),(g,2t+1),(g+8,2t),(g+8,2t+1)}
__device__ __forceinline__ void mma_tf32(float* d, const unsigned* a, const unsigned* b) {
    asm volatile(
        "mma.sync.aligned.m16n8k8.row.col.f32.tf32.tf32.f32 "
        "{%0,%1,%2,%3}, {%4,%5,%6,%7}, {%8,%9}, {%0,%1,%2,%3};\n"
        : "+f"(d[0]), "+f"(d[1]), "+f"(d[2]), "+f"(d[3])
        : "r"(a[0]), "r"(a[1]), "r"(a[2]), "r"(a[3]), "r"(b[0]), "r"(b[1]));
}

// ============================================================
// TF32 GEMM: C[M,N] = A[M,K] @ B[K,N] (+bias).
// Block 128x128, BK=32, 256 threads, 8 warps (2m x 4n), warp tile 64x32.
// A smem: pair-interleaved m-major As2[m][perm(k)], LDA=40 (64-bit frag loads).
// B smem: k-major Bs[k][132] (scalar frag loads, conflict-light).
// ============================================================
#define GLDA 40
template <bool BIAS>
__global__ __launch_bounds__(256) void gemm_tf32(
    const float* __restrict__ A, const float* __restrict__ B,
    const float* __restrict__ bias, float* __restrict__ Cm,
    int M, int N, int K) {
    __shared__ unsigned As2[128 * GLDA];
    __shared__ unsigned Bs[32][132];

    int tid = threadIdx.x;
    int lane = tid & 31, w = tid >> 5;
    int g = lane >> 2, t4 = lane & 3;
    int wm = (w & 1) * 64, wn = (w >> 1) * 32;
    int bm = blockIdx.y * 128, bn = blockIdx.x * 128;

    const int a_r = tid >> 3, a_k = (tid & 7) * 4;     // A: 32 rows x 8 float4 (x4 ii)
    const int a_c = a_k >> 3, a_e = (a_k >> 2) & 1;
    const int b_r = tid >> 5, b_c = (tid & 31) * 4;    // B: 8 rows (x4 ii) x 32 float4

    float acc[4][4][4];
#pragma unroll
    for (int i = 0; i < 4; i++)
#pragma unroll
        for (int j = 0; j < 4; j++)
#pragma unroll
            for (int r = 0; r < 4; r++) acc[i][j][r] = 0.f;

    float4 areg[4], breg[4];
#pragma unroll
    for (int ii = 0; ii < 4; ii++) {
        areg[ii] = *(const float4*)&A[(size_t)(bm + a_r + 32 * ii) * K + a_k];
        breg[ii] = *(const float4*)&B[(size_t)(b_r + 8 * ii) * N + bn + b_c];
    }

    for (int k0 = 0; k0 < K; k0 += 32) {
        __syncthreads();
#pragma unroll
        for (int ii = 0; ii < 4; ii++) {
            unsigned* ad = &As2[(a_r + 32 * ii) * GLDA + 8 * a_c + a_e];
            ad[0] = f2tf(areg[ii].x);
            ad[2] = f2tf(areg[ii].y);
            ad[4] = f2tf(areg[ii].z);
            ad[6] = f2tf(areg[ii].w);
            uint4 bv;
            bv.x = f2tf(breg[ii].x); bv.y = f2tf(breg[ii].y);
            bv.z = f2tf(breg[ii].z); bv.w = f2tf(breg[ii].w);
            *(uint4*)&Bs[b_r + 8 * ii][b_c] = bv;
        }
        __syncthreads();
        if (k0 + 32 < K) {
            int kn = k0 + 32;
#pragma unroll
            for (int ii = 0; ii < 4; ii++) {
                areg[ii] = *(const float4*)&A[(size_t)(bm + a_r + 32 * ii) * K + kn + a_k];
                breg[ii] = *(const float4*)&B[(size_t)(kn + b_r + 8 * ii) * N + bn + b_c];
            }
        }
#pragma unroll
        for (int c = 0; c < 4; c++) {
            unsigned af[4][4], bf[4][2];
#pragma unroll
            for (int i = 0; i < 4; i++) {
                uint2 lo = *(uint2*)&As2[(wm + 16 * i + g) * GLDA + 8 * c + 2 * t4];
                uint2 hi = *(uint2*)&As2[(wm + 16 * i + g + 8) * GLDA + 8 * c + 2 * t4];
                af[i][0] = lo.x; af[i][1] = hi.x; af[i][2] = lo.y; af[i][3] = hi.y;
            }
#pragma unroll
            for (int j = 0; j < 4; j++) {
                bf[j][0] = Bs[c * 8 + t4][wn + 8 * j + g];
                bf[j][1] = Bs[c * 8 + t4 + 4][wn + 8 * j + g];
            }
#pragma unroll
            for (int i = 0; i < 4; i++)
#pragma unroll
                for (int j = 0; j < 4; j++)
                    mma_tf32(acc[i][j], af[i], bf[j]);
        }
    }

#pragma unroll
    for (int i = 0; i < 4; i++)
#pragma unroll
        for (int j = 0; j < 4; j++) {
            int row = bm + wm + 16 * i + g;
            int col = bn + wn + 8 * j + 2 * t4;
            float2 v0 = make_float2(acc[i][j][0], acc[i][j][1]);
            float2 v1 = make_float2(acc[i][j][2], acc[i][j][3]);
            if (BIAS) {
                float2 bb = *(const float2*)&bias[col];
                v0.x += bb.x; v0.y += bb.y; v1.x += bb.x; v1.y += bb.y;
            }
            *(float2*)&Cm[(size_t)row * N + col] = v0;
            *(float2*)&Cm[(size_t)(row + 8) * N + col] = v1;
        }
}

// ============================================================
// Relative position bias (unchanged from R3).
// ============================================================
__global__ __launch_bounds__(256) void relpos_kernel(
    const float* __restrict__ rph, const float* __restrict__ rpw) {
    __shared__ float Rh[63 * 68], Rw[63 * 68];
    int tid = threadIdx.x;
    int qc = blockIdx.x, bh = blockIdx.y;

    for (int idx = tid; idx < 63 * 64; idx += 256) {
        int row = idx >> 6, d = idx & 63;
        Rh[row * 68 + d] = rph[idx];
        Rw[row * 68 + d] = rpw[idx];
    }
    __syncthreads();

    int ql = tid >> 1, half = tid & 1;
    int q = qc * 128 + ql;
    int b = bh / NH, head = bh % NH;
    int pc = half ? (q & 31) : (q >> 5);
    const float* qptr = &g_qkv[(size_t)(b * SEQ + q) * QKVLD + head * HD];
    const float* T = half ? Rw : Rh;

    float acc[32];
#pragma unroll
    for (int o = 0; o < 32; o++) acc[o] = 0.f;

    for (int d0 = 0; d0 < 64; d0 += 8) {
        float4 v0 = *(const float4*)&qptr[d0];
        float4 v1 = *(const float4*)&qptr[d0 + 4];
        float qd[8] = {v0.x, v0.y, v0.z, v0.w, v1.x, v1.y, v1.z, v1.w};
#pragma unroll
        for (int dd = 0; dd < 8; dd++) {
            float qv = qd[dd];
            const float* Tp = &T[(pc + 31) * 68 + d0 + dd];
#pragma unroll
            for (int o = 0; o < 32; o++)
                acc[o] = fmaf(qv, Tp[-o * 68], acc[o]);
        }
    }
    float* dst = half ? &g_relw[((size_t)bh * SEQ + q) * 32]
                      : &g_relh[((size_t)bh * SEQ + q) * 32];
#pragma unroll
    for (int o = 0; o < 32; o++) dst[o] = acc[o];
}

// ============================================================
// Flash attention, warp-local softmax. Bq=128, Bk=64, 256 thr, 8 warps.
// Warp w owns q-rows [w*16, w*16+16) across full 64 kv cols.
// Q A-frags in registers; K & P pair-interleaved smem; V pad-72.
// ============================================================
#define BQ 128
#define LDK 72
#define LDV 72
#define LDP 72
#define LDH 33
#define ATTN_SMEM ((64 * LDK + 64 * LDV + 8 * 16 * LDP + BQ * LDH) * 4)

__global__ __launch_bounds__(256, 2) void attn_mma() {
    extern __shared__ unsigned smu[];
    unsigned* Ks2 = smu;                    // [64][LDK]  n-major, perm(k)
    unsigned* Vs  = Ks2 + 64 * LDK;         // [64][LDV]  key-major, d cols
    unsigned* Pw  = Vs + 64 * LDV;          // 8 x [16][LDP] per-warp, perm(k)
    float* Bhs    = (float*)(Pw + 8 * 16 * LDP);  // [BQ][LDH] relh * log2e

    int tid = threadIdx.x;
    int lane = tid & 31, w = tid >> 5;
    int g = lane >> 2, t4 = lane & 3;

    int bh = blockIdx.y, qbase = blockIdx.x * BQ;
    int b = bh / NH, head = bh % NH;
    const float* base = &g_qkv[(size_t)b * SEQ * QKVLD + head * HD];

    // stage relh (scaled to log2 domain)
    {
        const float* gh = &g_relh[((size_t)bh * SEQ + qbase) * 32];
        for (int idx = tid; idx < BQ * 32; idx += 256) {
            int r = idx >> 5, c = idx & 31;
            Bhs[r * LDH + c] = LOG2E * gh[r * 32 + c];
        }
    }

    int qr0 = w * 16 + g;      // local q row (a0/a2)
    int qr1 = qr0 + 8;         // (a1/a3)

    // Q fragments (resident all iterations)
    unsigned qa[8][4];
    {
        const float* qp0 = base + (size_t)(qbase + qr0) * QKVLD;
        const float* qp1 = base + (size_t)(qbase + qr1) * QKVLD;
#pragma unroll
        for (int c = 0; c < 8; c++) {
            qa[c][0] = f2tf(qp0[8 * c + t4]);
            qa[c][1] = f2tf(qp1[8 * c + t4]);
            qa[c][2] = f2tf(qp0[8 * c + t4 + 4]);
            qa[c][3] = f2tf(qp1[8 * c + t4 + 4]);
        }
    }
    // relw registers (iteration-invariant column pattern), log2 domain
    float rw0[8], rw1[8];
    {
        const float* p0 = &g_relw[((size_t)bh * SEQ + qbase + qr0) * 32];
        const float* p1 = &g_relw[((size_t)bh * SEQ + qbase + qr1) * 32];
#pragma unroll
        for (int m = 0; m < 4; m++) {
            rw0[2 * m]     = LOG2E * p0[8 * m + 2 * t4];
            rw0[2 * m + 1] = LOG2E * p0[8 * m + 2 * t4 + 1];
            rw1[2 * m]     = LOG2E * p1[8 * m + 2 * t4];
            rw1[2 * m + 1] = LOG2E * p1[8 * m + 2 * t4 + 1];
        }
    }

    float m0 = -1e30f, m1 = -1e30f, l0 = 0.f, l1 = 0.f;
    float oacc[8][4];
#pragma unroll
    for (int nb = 0; nb < 8; nb++)
#pragma unroll
        for (int r = 0; r < 4; r++) oacc[nb][r] = 0.f;

    const int r_ = tid >> 4, d4 = (tid & 15) * 4;
    const int cc_ = d4 >> 3, ee_ = (d4 >> 2) & 1;
    // perm8 positions for P store: cols 2t4, 2t4+1
    const int i0 = 2 * ((2 * t4) & 3) + ((2 * t4) >> 2);
    const int i1 = 2 * ((2 * t4 + 1) & 3) + ((2 * t4 + 1) >> 2);
    unsigned* Pme = Pw + w * 16 * LDP;
    const float sc = 0.125f * LOG2E;

    for (int kt = 0; kt < 16; kt++) {
        __syncthreads();
        // fill K (perm-interleaved) and V (row-major) tiles
#pragma unroll
        for (int ii = 0; ii < 4; ii++) {
            int row = r_ + 16 * ii;
            const float* kp = base + (size_t)(kt * 64 + row) * QKVLD + CH + d4;
            float4 kv = *(const float4*)kp;
            unsigned* kd = &Ks2[row * LDK + 8 * cc_ + ee_];
            kd[0] = f2tf(kv.x); kd[2] = f2tf(kv.y);
            kd[4] = f2tf(kv.z); kd[6] = f2tf(kv.w);
            float4 vv = *(const float4*)(kp + CH);
            uint4 u;
            u.x = f2tf(vv.x); u.y = f2tf(vv.y); u.z = f2tf(vv.z); u.w = f2tf(vv.w);
            *(uint4*)&Vs[row * LDV + d4] = u;
        }
        __syncthreads();

        // S = Q K^T over the warp's 16 rows x 64 cols
        float sacc[8][4];
#pragma unroll
        for (int nb = 0; nb < 8; nb++)
#pragma unroll
            for (int r = 0; r < 4; r++) sacc[nb][r] = 0.f;
#pragma unroll
        for (int c = 0; c < 8; c++) {
#pragma unroll
            for (int nb = 0; nb < 8; nb++) {
                uint2 bb2 = *(uint2*)&Ks2[(8 * nb + g) * LDK + 8 * c + 2 * t4];
                unsigned bb[2] = {bb2.x, bb2.y};
                mma_tf32(sacc[nb], qa[c], bb);
            }
        }

        // bias + warp-local online softmax (log2 domain)
        float rh0a = Bhs[qr0 * LDH + 2 * kt], rh0b = Bhs[qr0 * LDH + 2 * kt + 1];
        float rh1a = Bhs[qr1 * LDH + 2 * kt], rh1b = Bhs[qr1 * LDH + 2 * kt + 1];
        float mn0 = m0, mn1 = m1;
#pragma unroll
        for (int nb = 0; nb < 8; nb++) {
            float bh0 = nb < 4 ? rh0a : rh0b;
            float bh1 = nb < 4 ? rh1a : rh1b;
            int mi = nb & 3;
            sacc[nb][0] = fmaf(sc, sacc[nb][0], bh0 + rw0[2 * mi]);
            sacc[nb][1] = fmaf(sc, sacc[nb][1], bh0 + rw0[2 * mi + 1]);
            sacc[nb][2] = fmaf(sc, sacc[nb][2], bh1 + rw1[2 * mi]);
            sacc[nb][3] = fmaf(sc, sacc[nb][3], bh1 + rw1[2 * mi + 1]);
            mn0 = fmaxf(mn0, fmaxf(sacc[nb][0], sacc[nb][1]));
            mn1 = fmaxf(mn1, fmaxf(sacc[nb][2], sacc[nb][3]));
        }
        mn0 = fmaxf(mn0, __shfl_xor_sync(0xffffffffu, mn0, 1));
        mn0 = fmaxf(mn0, __shfl_xor_sync(0xffffffffu, mn0, 2));
        mn1 = fmaxf(mn1, __shfl_xor_sync(0xffffffffu, mn1, 1));
        mn1 = fmaxf(mn1, __shfl_xor_sync(0xffffffffu, mn1, 2));
        float cr0 = ex2(m0 - mn0), cr1 = ex2(m1 - mn1);
        m0 = mn0; m1 = mn1;
        float s0 = 0.f, s1 = 0.f;
#pragma unroll
        for (int nb = 0; nb < 8; nb++) {
            float p0 = ex2(sacc[nb][0] - mn0);
            float p1 = ex2(sacc[nb][1] - mn0);
            float p2 = ex2(sacc[nb][2] - mn1);
            float p3 = ex2(sacc[nb][3] - mn1);
            s0 += p0 + p1; s1 += p2 + p3;
            unsigned* pr = &Pme[8 * nb];
            pr[g * LDP + i0] = f2tf(p0);
            pr[g * LDP + i1] = f2tf(p1);
            pr[(g + 8) * LDP + i0] = f2tf(p2);
            pr[(g + 8) * LDP + i1] = f2tf(p3);
        }
        s0 += __shfl_xor_sync(0xffffffffu, s0, 1);
        s0 += __shfl_xor_sync(0xffffffffu, s0, 2);
        s1 += __shfl_xor_sync(0xffffffffu, s1, 1);
        s1 += __shfl_xor_sync(0xffffffffu, s1, 2);
        l0 = l0 * cr0 + s0;
        l1 = l1 * cr1 + s1;
#pragma unroll
        for (int nb = 0; nb < 8; nb++) {
            oacc[nb][0] *= cr0; oacc[nb][1] *= cr0;
            oacc[nb][2] *= cr1; oacc[nb][3] *= cr1;
        }
        __syncwarp();

        // O += P @ V
#pragma unroll
        for (int c = 0; c < 8; c++) {
            uint2 lo = *(uint2*)&Pme[g * LDP + 8 * c + 2 * t4];
            uint2 hi = *(uint2*)&Pme[(g + 8) * LDP + 8 * c + 2 * t4];
            unsigned pa[4] = {lo.x, hi.x, lo.y, hi.y};
            const unsigned* v0 = &Vs[(8 * c + t4) * LDV];
            const unsigned* v1 = &Vs[(8 * c + t4 + 4) * LDV];
#pragma unroll
            for (int nb = 0; nb < 8; nb++) {
                unsigned bb[2] = {v0[8 * nb + g], v1[8 * nb + g]};
                mma_tf32(oacc[nb], pa, bb);
            }
        }
    }

    // normalize + write (B,S,C) layout
    float inv0 = 1.f / l0, inv1 = 1.f / l1;
    float* op0 = &g_attn[(size_t)(b * SEQ + qbase + qr0) * CH + head * HD + 2 * t4];
    float* op1 = &g_attn[(size_t)(b * SEQ + qbase + qr1) * CH + head * HD + 2 * t4];
#pragma unroll
    for (int nb = 0; nb < 8; nb++) {
        *(float2*)&op0[8 * nb] = make_float2(oacc[nb][0] * inv0, oacc[nb][1] * inv0);
        *(float2*)&op1[8 * nb] = make_float2(oacc[nb][2] * inv1, oacc[nb][3] * inv1);
    }
}

// ============================================================
extern "C" void kernel_launch(void* const* d_in, const int* in_sizes, int n_in,
                              void* d_out, int out_size) {
    const float* x     = (const float*)d_in[0];
    const float* Wqkv  = (const float*)d_in[1];
    const float* Wproj = (const float*)d_in[2];
    const float* bproj = (const float*)d_in[3];
    const float* rph   = (const float*)d_in[4];
    const float* rpw   = (const float*)d_in[5];
    float* out = (float*)d_out;

    float* qkv;  cudaGetSymbolAddress((void**)&qkv,  g_qkv);
    float* attn; cudaGetSymbolAddress((void**)&attn, g_attn);

    // 1) QKV projection: (4096 x 2304) = (4096 x 768) @ (768 x 2304)
    gemm_tf32<false><<<dim3(QKVLD / 128, (NB * SEQ) / 128), 256>>>(
        x, Wqkv, nullptr, qkv, NB * SEQ, QKVLD, CH);

    // 2) decomposed relative position bias
    relpos_kernel<<<dim3(8, BHD), 256>>>(rph, rpw);

    // 3) attention (tf32 mma, warp-local online softmax)
    cudaFuncSetAttribute(attn_mma, cudaFuncAttributeMaxDynamicSharedMemorySize, ATTN_SMEM);
    attn_mma<<<dim3(SEQ / BQ, BHD), 256, ATTN_SMEM>>>();

    // 4) out projection + bias: (4096 x 768) = (4096 x 768) @ (768 x 768) + b
    gemm_tf32<true><<<dim3(CH / 128, (NB * SEQ) / 128), 256>>>(
        attn, Wproj, bproj, out, NB * SEQ, CH, CH);
}